// round 2
// baseline (speedup 1.0000x reference)
#include <cuda_runtime.h>
#include <math.h>

#define BATCH 512
#define SEQ   256
#define EMBED 384
#define HDIM  64
#define NROWS (BATCH * SEQ)   // 131072

typedef unsigned long long ull;

// packed f32x2 helpers (SASS FFMA2 path — not emitted by ptxas from C++)
#define FFMA2(d,a,bb,c) asm("fma.rn.f32x2 %0, %1, %2, %3;" : "=l"(d) : "l"(a), "l"(bb), "l"(c))
#define MULX2(d,a,bb)   asm("mul.rn.f32x2 %0, %1, %2;"     : "=l"(d) : "l"(a), "l"(bb))
#define PACK2(d,x)      asm("mov.b64 %0, {%1, %1};"        : "=l"(d) : "f"(x))
#define UNPK(lo,hi,p)   asm("mov.b64 {%0, %1}, %2;"        : "=f"(lo), "=f"(hi) : "l"(p))

// Scratch for projected Q/K/V.
__device__ float g_Q[(size_t)NROWS * HDIM];
__device__ float g_K[(size_t)NROWS * HDIM];
__device__ float g_V[(size_t)NROWS * HDIM];

// ---------------------------------------------------------------------------
// Projection GEMM: [131072, 384] x [384, 64] (x3 fused in N) -> g_Q/g_K/g_V
// Block tile 128(M) x 192(N), K-chunk 32. 384 threads (16 x 24).
// Micro-tile 8 rows x 8 cols, cols as two 4-col chunks (tx*4, tx*4+96) so the
// b-fragment LDS.128s are conflict-free. Accumulators packed f32x2 in c-dim.
// ---------------------------------------------------------------------------
#define PBM 128
#define PBK 32
#define PTHREADS 384

__global__ __launch_bounds__(PTHREADS) void proj_kernel(
    const float* __restrict__ X,
    const float* __restrict__ Wq,
    const float* __restrict__ Wk,
    const float* __restrict__ Wv)
{
    __shared__ float Xs[PBK][PBM + 1];   // transposed: Xs[k][row]
    __shared__ float Ws[PBK][192];       // Q | K | V columns

    const int tid = threadIdx.x;
    const int ty = tid / 24;             // 0..15 -> row group (8 rows)
    const int tx = tid % 24;             // 0..23 -> col group
    const int row0 = blockIdx.x * PBM;

    ull acc[8][4];                       // [row][packed col pair]
#pragma unroll
    for (int r = 0; r < 8; ++r)
#pragma unroll
        for (int c = 0; c < 4; ++c) acc[r][c] = 0ULL;

    for (int k0 = 0; k0 < EMBED; k0 += PBK) {
        // --- load X tile (128 x 32), transpose into smem ---
        for (int idx = tid; idx < PBM * (PBK / 4); idx += PTHREADS) {
            const int r  = idx >> 3;     // 0..127
            const int kq = idx & 7;      // 0..7
            const float4 v = *(const float4*)(X + (size_t)(row0 + r) * EMBED + k0 + kq * 4);
            Xs[kq * 4 + 0][r] = v.x;
            Xs[kq * 4 + 1][r] = v.y;
            Xs[kq * 4 + 2][r] = v.z;
            Xs[kq * 4 + 3][r] = v.w;
        }
        // --- load W tile (32 x 192) ---
        for (int idx = tid; idx < PBK * 48; idx += PTHREADS) {
            const int kk = idx / 48;
            const int c4 = idx % 48;
            const float* Wm = (c4 < 16) ? Wq : ((c4 < 32) ? Wk : Wv);
            const int d4 = c4 & 15;
            const float4 v = *(const float4*)(Wm + (size_t)(k0 + kk) * HDIM + d4 * 4);
            *(float4*)(&Ws[kk][c4 * 4]) = v;
        }
        __syncthreads();

#pragma unroll 4
        for (int k = 0; k < PBK; ++k) {
            // b pairs: direct register aliasing of LDS.128 (conflict-free: 16B/lane)
            const ulonglong2 b01 = *(const ulonglong2*)(&Ws[k][tx * 4]);
            const ulonglong2 b23 = *(const ulonglong2*)(&Ws[k][96 + tx * 4]);
            const ull bp[4] = {b01.x, b01.y, b23.x, b23.y};
            // a: 8 scalar loads (warp-broadcast) + duplicate-pack
            ull ap[8];
#pragma unroll
            for (int r = 0; r < 8; ++r) {
                const float a = Xs[k][ty * 8 + r];
                PACK2(ap[r], a);
            }
#pragma unroll
            for (int r = 0; r < 8; ++r)
#pragma unroll
                for (int c = 0; c < 4; ++c)
                    FFMA2(acc[r][c], ap[r], bp[c], acc[r][c]);
        }
        __syncthreads();
    }

    // --- epilogue: two 4-col groups, each maps to one of Q/K/V ---
#pragma unroll
    for (int g = 0; g < 2; ++g) {
        const int gc0 = g * 96 + tx * 4;       // global fused column 0..191
        const int mat = gc0 >> 6;              // 0=Q, 1=K, 2=V
        float* Og = (mat == 0) ? g_Q : ((mat == 1) ? g_K : g_V);
        const int d0 = gc0 & 63;
#pragma unroll
        for (int r = 0; r < 8; ++r) {
            float4 v;
            UNPK(v.x, v.y, acc[r][2 * g + 0]);
            UNPK(v.z, v.w, acc[r][2 * g + 1]);
            *(float4*)(Og + (size_t)(row0 + ty * 8 + r) * HDIM + d0) = v;
        }
    }
}

// ---------------------------------------------------------------------------
// Attention: one block per (batch, 64-query tile). Whole K/V/Q/S in smem.
// Phase 1: 16 rows x 4 cols per thread, rows packed f32x2 (Q pairs free from
//          smem), scores stored TRANSPOSED St[j][i].
// Phase 3: 8 rows x 2 cols per thread, P row-pairs free from transposed St.
// ---------------------------------------------------------------------------
#define KT_LD 260
#define QT_LD 68
#define ST_LD 68

#define SM_KT 0
#define SM_VS (SM_KT + 64 * KT_LD)             // 16640
#define SM_QT (SM_VS + 256 * 64)               // 33024
#define SM_ST (SM_QT + 64 * QT_LD)             // 37376
#define SM_RI (SM_ST + 256 * ST_LD)            // 54784
#define SM_FLOATS (SM_RI + 64)                 // 54848
#define SM_BYTES  (SM_FLOATS * 4)              // 219392

__global__ __launch_bounds__(256) void attn_kernel(float* __restrict__ Out)
{
    extern __shared__ float sm[];
    float* Kt   = sm + SM_KT;   // [64 kd][KT_LD] transposed keys
    float* Vs   = sm + SM_VS;   // [256 j][64 d]
    float* Qt   = sm + SM_QT;   // [64 kd][QT_LD] transposed queries
    float* St   = sm + SM_ST;   // [256 j][ST_LD] transposed scores St[j][i]
    float* rinv = sm + SM_RI;   // [64] 1/rowsum

    const int tid = threadIdx.x;
    const int qt  = blockIdx.x;          // 0..3
    const int b   = blockIdx.y;          // 0..511
    const int kvlen = (qt + 1) * 64;

    const float* Kg = g_K + (size_t)b * SEQ * HDIM;
    const float* Vg = g_V + (size_t)b * SEQ * HDIM;
    const float* Qg = g_Q + ((size_t)b * SEQ + qt * 64) * HDIM;

    // --- load K transposed ---
    for (int idx = tid; idx < kvlen * 16; idx += 256) {
        const int j  = (idx & 31) + ((idx >> 9) << 5);
        const int q4 = (idx >> 5) & 15;
        const float4 v = *(const float4*)(Kg + (size_t)j * HDIM + q4 * 4);
        Kt[(q4 * 4 + 0) * KT_LD + j] = v.x;
        Kt[(q4 * 4 + 1) * KT_LD + j] = v.y;
        Kt[(q4 * 4 + 2) * KT_LD + j] = v.z;
        Kt[(q4 * 4 + 3) * KT_LD + j] = v.w;
    }
    // --- load V ---
    for (int idx = tid; idx < kvlen * 16; idx += 256)
        *(float4*)(Vs + idx * 4) = *(const float4*)(Vg + (size_t)idx * 4);
    // --- load Q transposed ---
    for (int idx = tid; idx < 64 * 16; idx += 256) {
        const int i  = (idx & 31) + ((idx >> 9) << 5);
        const int q4 = (idx >> 5) & 15;
        const float4 v = *(const float4*)(Qg + (size_t)i * HDIM + q4 * 4);
        Qt[(q4 * 4 + 0) * QT_LD + i] = v.x;
        Qt[(q4 * 4 + 1) * QT_LD + i] = v.y;
        Qt[(q4 * 4 + 2) * QT_LD + i] = v.z;
        Qt[(q4 * 4 + 3) * QT_LD + i] = v.w;
    }
    __syncthreads();

    const float scale = 0.125f;          // 1/sqrt(64)

    // --- phase 1: S = scale * Q K^T (causal), write transposed St[j][i] ---
    {
        const int ty1 = tid >> 6;        // 0..3
        const int tx1 = tid & 63;        // 0..63
        const int i0 = ty1 * 16;
        const int j0 = tx1 * 4;
        if (j0 < kvlen) {
            ull acc[8][4];               // [row pair][col]
#pragma unroll
            for (int r = 0; r < 8; ++r)
#pragma unroll
                for (int c = 0; c < 4; ++c) acc[r][c] = 0ULL;

#pragma unroll 4
            for (int kd = 0; kd < 64; ++kd) {
                const float* qrow = Qt + kd * QT_LD + i0;
                const ulonglong2 qa = *(const ulonglong2*)(qrow);
                const ulonglong2 qb = *(const ulonglong2*)(qrow + 4);
                const ulonglong2 qc = *(const ulonglong2*)(qrow + 8);
                const ulonglong2 qd = *(const ulonglong2*)(qrow + 12);
                const ull ap[8] = {qa.x, qa.y, qb.x, qb.y, qc.x, qc.y, qd.x, qd.y};
                const float4 kv4 = *(const float4*)(Kt + kd * KT_LD + j0);
                ull bp[4];
                PACK2(bp[0], kv4.x); PACK2(bp[1], kv4.y);
                PACK2(bp[2], kv4.z); PACK2(bp[3], kv4.w);
#pragma unroll
                for (int r = 0; r < 8; ++r)
#pragma unroll
                    for (int c = 0; c < 4; ++c)
                        FFMA2(acc[r][c], ap[r], bp[c], acc[r][c]);
            }

            const int qbase = qt * 64 + i0;
#pragma unroll
            for (int c = 0; c < 4; ++c) {
                const int j = j0 + c;
                float s[16];
#pragma unroll
                for (int r = 0; r < 8; ++r)
                    UNPK(s[2 * r], s[2 * r + 1], acc[r][c]);
                float* stc = St + j * ST_LD + i0;
#pragma unroll
                for (int m = 0; m < 4; ++m) {
                    float4 v;
                    v.x = (j <= qbase + 4 * m + 0) ? s[4 * m + 0] * scale : -3.0e38f;
                    v.y = (j <= qbase + 4 * m + 1) ? s[4 * m + 1] * scale : -3.0e38f;
                    v.z = (j <= qbase + 4 * m + 2) ? s[4 * m + 2] * scale : -3.0e38f;
                    v.w = (j <= qbase + 4 * m + 3) ? s[4 * m + 3] * scale : -3.0e38f;
                    *(float4*)(stc + 4 * m) = v;
                }
            }
        }
    }
    __syncthreads();

    // --- phase 2: softmax over j for each row i (4 threads per row) ---
    {
        const int row = tid >> 2;
        const int c   = tid & 3;
        float m = -3.4e38f;
        for (int j = c; j < kvlen; j += 4)
            m = fmaxf(m, St[j * ST_LD + row]);
        m = fmaxf(m, __shfl_xor_sync(0xffffffffu, m, 1));
        m = fmaxf(m, __shfl_xor_sync(0xffffffffu, m, 2));
        float ssum = 0.0f;
        for (int j = c; j < kvlen; j += 4) {
            const float e = __expf(St[j * ST_LD + row] - m);
            St[j * ST_LD + row] = e;
            ssum += e;
        }
        ssum += __shfl_xor_sync(0xffffffffu, ssum, 1);
        ssum += __shfl_xor_sync(0xffffffffu, ssum, 2);
        if (c == 0) rinv[row] = 1.0f / ssum;
    }
    __syncthreads();

    // --- phase 3: O = P V (rows packed f32x2, P pairs free from St) ---
    {
        const int ty3 = tid >> 5;        // 0..7
        const int tx3 = tid & 31;        // 0..31
        const int i0 = ty3 * 8;
        const int d0 = tx3 * 2;

        ull acc[4][2];
#pragma unroll
        for (int r = 0; r < 4; ++r) { acc[r][0] = 0ULL; acc[r][1] = 0ULL; }

#pragma unroll 4
        for (int j = 0; j < kvlen; ++j) {
            const float* prow = St + j * ST_LD + i0;
            const ulonglong2 pa = *(const ulonglong2*)(prow);
            const ulonglong2 pb = *(const ulonglong2*)(prow + 4);
            const ull ap[4] = {pa.x, pa.y, pb.x, pb.y};
            const float2 vv = *(const float2*)(Vs + j * 64 + d0);
            ull b0, b1;
            PACK2(b0, vv.x); PACK2(b1, vv.y);
#pragma unroll
            for (int r = 0; r < 4; ++r) {
                FFMA2(acc[r][0], ap[r], b0, acc[r][0]);
                FFMA2(acc[r][1], ap[r], b1, acc[r][1]);
            }
        }

        const ulonglong2 r01 = *(const ulonglong2*)(rinv + i0);
        const ulonglong2 r23 = *(const ulonglong2*)(rinv + i0 + 4);
        const ull rp[4] = {r01.x, r01.y, r23.x, r23.y};
#pragma unroll
        for (int r = 0; r < 4; ++r) {
            MULX2(acc[r][0], acc[r][0], rp[r]);
            MULX2(acc[r][1], acc[r][1], rp[r]);
        }

        float* Og = Out + ((size_t)b * SEQ + qt * 64 + i0) * HDIM + d0;
#pragma unroll
        for (int r = 0; r < 4; ++r) {
            float lo0, hi0, lo1, hi1;
            UNPK(lo0, hi0, acc[r][0]);
            UNPK(lo1, hi1, acc[r][1]);
            float2 v0; v0.x = lo0; v0.y = lo1;
            float2 v1; v1.x = hi0; v1.y = hi1;
            *(float2*)(Og + (size_t)(2 * r) * HDIM)     = v0;
            *(float2*)(Og + (size_t)(2 * r + 1) * HDIM) = v1;
        }
    }
}

// ---------------------------------------------------------------------------
extern "C" void kernel_launch(void* const* d_in, const int* in_sizes, int n_in,
                              void* d_out, int out_size)
{
    const float* X  = (const float*)d_in[0];   // [512,256,384]
    const float* Wk = (const float*)d_in[1];   // [384,64]
    const float* Wq = (const float*)d_in[2];   // [384,64]
    const float* Wv = (const float*)d_in[3];   // [384,64]
    float* Out = (float*)d_out;                // [512,256,64]

    (void)in_sizes; (void)n_in; (void)out_size;

    cudaFuncSetAttribute(attn_kernel,
                         cudaFuncAttributeMaxDynamicSharedMemorySize, SM_BYTES);

    proj_kernel<<<NROWS / PBM, PTHREADS>>>(X, Wq, Wk, Wv);

    dim3 grid(SEQ / 64, BATCH);
    attn_kernel<<<grid, 256, SM_BYTES>>>(Out);
}

// round 4
// speedup vs baseline: 1.9507x; 1.9507x over previous
#include <cuda_runtime.h>
#include <cuda_bf16.h>
#include <cstdint>

#define BATCH 512
#define SEQ   256
#define EMBED 384
#define HDIM  64
#define NROWS (BATCH * SEQ)   // 131072

typedef uint16_t half_t;

// ---------------------------------------------------------------------------
// Global scratch. Q and K stored TRANSPOSED per batch: [b][d][s].
// V stored normally: [row][d]. W split-bf16, layout [mat][n][k] (k=EMBED fast).
// ---------------------------------------------------------------------------
__device__ float g_Qt[(size_t)BATCH * HDIM * SEQ];
__device__ float g_Kt[(size_t)BATCH * HDIM * SEQ];
__device__ float g_V [(size_t)NROWS * HDIM];
__device__ __nv_bfloat16 g_Wh[3 * HDIM * EMBED];
__device__ __nv_bfloat16 g_Wl[3 * HDIM * EMBED];

// ---------------------------------------------------------------------------
// bf16 mma.sync helper (sm_80+ PTX; works on sm_103 plain target)
// ---------------------------------------------------------------------------
__device__ __forceinline__ void mma_bf16(float* d, const uint32_t* a,
                                         uint32_t b0, uint32_t b1) {
    asm volatile(
        "mma.sync.aligned.m16n8k16.row.col.f32.bf16.bf16.f32 "
        "{%0,%1,%2,%3}, {%4,%5,%6,%7}, {%8,%9}, {%0,%1,%2,%3};"
        : "+f"(d[0]), "+f"(d[1]), "+f"(d[2]), "+f"(d[3])
        : "r"(a[0]), "r"(a[1]), "r"(a[2]), "r"(a[3]), "r"(b0), "r"(b1));
}

// ---------------------------------------------------------------------------
// W convert: [E,D] fp32 -> g_Wh/g_Wl [mat][n=d][k=e] split bf16 (transposed)
// ---------------------------------------------------------------------------
__global__ void wconv_kernel(const float* __restrict__ Wq,
                             const float* __restrict__ Wk,
                             const float* __restrict__ Wv)
{
    const int idx = blockIdx.x * 256 + threadIdx.x;   // 73728 total
    const int mat = idx / (HDIM * EMBED);
    const int rem = idx % (HDIM * EMBED);
    const int n = rem / EMBED;
    const int k = rem % EMBED;
    const float* W = (mat == 0) ? Wq : ((mat == 1) ? Wk : Wv);
    const float w = W[(size_t)k * HDIM + n];
    const __nv_bfloat16 hi = __float2bfloat16(w);
    const __nv_bfloat16 lo = __float2bfloat16(w - __bfloat162float(hi));
    g_Wh[idx] = hi;
    g_Wl[idx] = lo;
}

// ---------------------------------------------------------------------------
// Projection via HMMA: per CTA M=128, N=192 (Q|K|V), K=384 in 6 chunks of 64.
// 8 warps = 4(m) x 2(n); warp tile 32 x 96. Split-bf16: acc += Ah*Bh + Ah*Bl
// + Al*Bh. Epilogue stages through smem, writes Q/K transposed.
// ---------------------------------------------------------------------------
#define AK_LD 72                 // halves per A row (64 + 8 pad)
#define OFF_AH 0
#define OFF_AL (OFF_AH + 128 * AK_LD)            // halves
#define OFF_BH (OFF_AL + 128 * AK_LD)
#define OFF_BL (OFF_BH + 192 * AK_LD)
#define MMA_SMEM_HALVES (OFF_BL + 192 * AK_LD)   // 46080 halves = 92160 B
#define ST_LD 196                                 // stage row stride (floats)
#define PJ_SMEM_BYTES (128 * ST_LD * 4 > MMA_SMEM_HALVES * 2 ? 128 * ST_LD * 4 : MMA_SMEM_HALVES * 2)

__global__ __launch_bounds__(256) void proj_kernel(const float* __restrict__ X)
{
    extern __shared__ char smraw[];
    half_t* Ah = (half_t*)(smraw) + OFF_AH;
    half_t* Al = (half_t*)(smraw) + OFF_AL;
    half_t* Bh = (half_t*)(smraw) + OFF_BH;
    half_t* Bl = (half_t*)(smraw) + OFF_BL;
    float*  stage = (float*)smraw;               // union, used after mma loop

    const int tid = threadIdx.x;
    const int lane = tid & 31;
    const int wid = tid >> 5;
    const int warp_m = wid & 3;                  // 0..3 -> rows of 32
    const int warp_n = wid >> 2;                 // 0..1 -> fused cols of 96
    const int row0 = blockIdx.x * 128;

    float acc[2][12][4];
#pragma unroll
    for (int mt = 0; mt < 2; ++mt)
#pragma unroll
        for (int nt = 0; nt < 12; ++nt)
#pragma unroll
            for (int i = 0; i < 4; ++i) acc[mt][nt][i] = 0.0f;

    const int r_fr = lane >> 2;                  // 0..7
    const int c_fr = (lane & 3) * 2;             // 0,2,4,6

    for (int c = 0; c < 6; ++c) {
        // --- A: X[128][64] fp32 -> split bf16 into Ah/Al ---
#pragma unroll
        for (int i = 0; i < 8; ++i) {
            const int idx = i * 256 + tid;
            const int m = idx >> 4;
            const int c4 = (idx & 15) * 4;
            const float4 v = *(const float4*)(X + (size_t)(row0 + m) * EMBED + c * 64 + c4);
            const __nv_bfloat162 h01 = __floats2bfloat162_rn(v.x, v.y);
            const __nv_bfloat162 h23 = __floats2bfloat162_rn(v.z, v.w);
            const __nv_bfloat162 l01 = __floats2bfloat162_rn(
                v.x - __bfloat162float(h01.x), v.y - __bfloat162float(h01.y));
            const __nv_bfloat162 l23 = __floats2bfloat162_rn(
                v.z - __bfloat162float(h23.x), v.w - __bfloat162float(h23.y));
            uint2 hv, lv;
            hv.x = *(const uint32_t*)&h01; hv.y = *(const uint32_t*)&h23;
            lv.x = *(const uint32_t*)&l01; lv.y = *(const uint32_t*)&l23;
            *(uint2*)(Ah + m * AK_LD + c4) = hv;
            *(uint2*)(Al + m * AK_LD + c4) = lv;
        }
        // --- B: g_Wh/g_Wl [n=0..191][k chunk] -> Bs ---
#pragma unroll
        for (int i = 0; i < 6; ++i) {
            const int idx = i * 256 + tid;       // 1536 total
            const int n = idx >> 3;
            const int q = idx & 7;
            const size_t gb = (size_t)n * EMBED + c * 64 + q * 8;
            *(float4*)(Bh + n * AK_LD + q * 8) = *(const float4*)((const half_t*)g_Wh + gb);
            *(float4*)(Bl + n * AK_LD + q * 8) = *(const float4*)((const half_t*)g_Wl + gb);
        }
        __syncthreads();

#pragma unroll
        for (int ks = 0; ks < 4; ++ks) {
            const int kc = ks * 16 + c_fr;
            uint32_t ah[2][4], al[2][4];
#pragma unroll
            for (int mt = 0; mt < 2; ++mt) {
                const int mb = warp_m * 32 + mt * 16;
                ah[mt][0] = *(const uint32_t*)(Ah + (mb + r_fr) * AK_LD + kc);
                ah[mt][1] = *(const uint32_t*)(Ah + (mb + r_fr + 8) * AK_LD + kc);
                ah[mt][2] = *(const uint32_t*)(Ah + (mb + r_fr) * AK_LD + kc + 8);
                ah[mt][3] = *(const uint32_t*)(Ah + (mb + r_fr + 8) * AK_LD + kc + 8);
                al[mt][0] = *(const uint32_t*)(Al + (mb + r_fr) * AK_LD + kc);
                al[mt][1] = *(const uint32_t*)(Al + (mb + r_fr + 8) * AK_LD + kc);
                al[mt][2] = *(const uint32_t*)(Al + (mb + r_fr) * AK_LD + kc + 8);
                al[mt][3] = *(const uint32_t*)(Al + (mb + r_fr + 8) * AK_LD + kc + 8);
            }
#pragma unroll
            for (int nt = 0; nt < 12; ++nt) {
                const int nb = warp_n * 96 + nt * 8 + r_fr;
                const uint32_t bh0 = *(const uint32_t*)(Bh + nb * AK_LD + kc);
                const uint32_t bh1 = *(const uint32_t*)(Bh + nb * AK_LD + kc + 8);
                const uint32_t bl0 = *(const uint32_t*)(Bl + nb * AK_LD + kc);
                const uint32_t bl1 = *(const uint32_t*)(Bl + nb * AK_LD + kc + 8);
                mma_bf16(acc[0][nt], ah[0], bh0, bh1);
                mma_bf16(acc[1][nt], ah[1], bh0, bh1);
                mma_bf16(acc[0][nt], ah[0], bl0, bl1);
                mma_bf16(acc[1][nt], ah[1], bl0, bl1);
                mma_bf16(acc[0][nt], al[0], bh0, bh1);
                mma_bf16(acc[1][nt], al[1], bh0, bh1);
            }
        }
        __syncthreads();
    }

    // --- stage accumulators to smem: stage[m][fused_col] ---
#pragma unroll
    for (int mt = 0; mt < 2; ++mt) {
        const int r0 = warp_m * 32 + mt * 16 + r_fr;
#pragma unroll
        for (int nt = 0; nt < 12; ++nt) {
            const int col = warp_n * 96 + nt * 8 + c_fr;
            float2 v0, v1;
            v0.x = acc[mt][nt][0]; v0.y = acc[mt][nt][1];
            v1.x = acc[mt][nt][2]; v1.y = acc[mt][nt][3];
            *(float2*)(stage + r0 * ST_LD + col)       = v0;
            *(float2*)(stage + (r0 + 8) * ST_LD + col) = v1;
        }
    }
    __syncthreads();

    // --- Q/K: transposed coalesced stores; V: normal layout ---
    const int b = row0 >> 8;
    const int sbase = row0 & 255;
    // Q (cols 0..63) and K (cols 64..127): g_{Q,K}t[b][d][s]
    for (int idx = tid; idx < 4096; idx += 256) {
        const int d = idx >> 5;                  // 0..127 fused (Q then K)
        const int s0 = (idx & 31) * 4;
        float4 v;
        v.x = stage[(s0 + 0) * ST_LD + d];
        v.y = stage[(s0 + 1) * ST_LD + d];
        v.z = stage[(s0 + 2) * ST_LD + d];
        v.w = stage[(s0 + 3) * ST_LD + d];
        float* dst = (d < 64)
            ? (g_Qt + (size_t)b * HDIM * SEQ + d * SEQ + sbase + s0)
            : (g_Kt + (size_t)b * HDIM * SEQ + (d - 64) * SEQ + sbase + s0);
        *(float4*)dst = v;
    }
    // V (cols 128..191): g_V[row][d]
    for (int idx = tid; idx < 2048; idx += 256) {
        const int m = idx >> 4;
        const int q = idx & 15;
        float4 v = *(const float4*)(stage + m * ST_LD + 128 + q * 4);
        *(float4*)(g_V + (size_t)(row0 + m) * HDIM + q * 4) = v;
    }
}

// ---------------------------------------------------------------------------
// Attention (measured-good scalar core). One block per (batch, 64-query tile).
// ---------------------------------------------------------------------------
#define KT_LD  260
#define QT_LD  68
#define SS_LD  257

#define SM_KT   0
#define SM_VS   (SM_KT + 64 * KT_LD)
#define SM_QT   (SM_VS + 256 * 64)
#define SM_SS   (SM_QT + 64 * QT_LD)
#define SM_RI   (SM_SS + 64 * SS_LD)
#define SM_FLOATS (SM_RI + 64)
#define SM_BYTES  (SM_FLOATS * 4)   // 215552

__global__ __launch_bounds__(256) void attn_kernel(float* __restrict__ Out)
{
    extern __shared__ float smf[];
    float* Kt   = smf + SM_KT;
    float* Vs   = smf + SM_VS;
    float* Qt   = smf + SM_QT;
    float* Ss   = smf + SM_SS;
    float* rinv = smf + SM_RI;

    const int tid = threadIdx.x;
    const int qt  = blockIdx.x;
    const int b   = blockIdx.y;
    const int kvlen = (qt + 1) * 64;

    const float* Ktg = g_Kt + (size_t)b * HDIM * SEQ;   // [64][256]
    const float* Qtg = g_Qt + (size_t)b * HDIM * SEQ;
    const float* Vg  = g_V  + (size_t)b * SEQ * HDIM;

    // --- K: straight strided copy (already transposed in gmem) ---
    const int kq4 = kvlen / 4;
    for (int idx = tid; idx < 64 * kq4; idx += 256) {
        const int kd = idx / kq4;
        const int j4 = (idx % kq4) * 4;
        *(float4*)(Kt + kd * KT_LD + j4) = *(const float4*)(Ktg + kd * SEQ + j4);
    }
    // --- V ---
    for (int idx = tid; idx < kvlen * 16; idx += 256)
        *(float4*)(Vs + idx * 4) = *(const float4*)(Vg + (size_t)idx * 4);
    // --- Q ---
    for (int idx = tid; idx < 64 * 16; idx += 256) {
        const int kd = idx >> 4;
        const int i4 = (idx & 15) * 4;
        *(float4*)(Qt + kd * QT_LD + i4) =
            *(const float4*)(Qtg + kd * SEQ + qt * 64 + i4);
    }
    __syncthreads();

    const int i0 = (tid / 16) * 4;
    const int tx = tid % 16;
    const float scale = 0.125f;

    // --- phase 1: S = scale * Q K^T, causal-masked ---
    for (int jt = 0; jt <= qt; ++jt) {
        const int j0 = jt * 64 + tx * 4;
        float acc[4][4];
#pragma unroll
        for (int r = 0; r < 4; ++r)
#pragma unroll
            for (int c = 0; c < 4; ++c) acc[r][c] = 0.0f;

#pragma unroll 16
        for (int kd = 0; kd < 64; ++kd) {
            const float4 av = *(const float4*)(Qt + kd * QT_LD + i0);
            const float4 bv = *(const float4*)(Kt + kd * KT_LD + j0);
            const float a[4] = {av.x, av.y, av.z, av.w};
            const float bb[4] = {bv.x, bv.y, bv.z, bv.w};
#pragma unroll
            for (int r = 0; r < 4; ++r)
#pragma unroll
                for (int c = 0; c < 4; ++c)
                    acc[r][c] = fmaf(a[r], bb[c], acc[r][c]);
        }
#pragma unroll
        for (int r = 0; r < 4; ++r) {
            const int qglob = qt * 64 + i0 + r;
#pragma unroll
            for (int c = 0; c < 4; ++c) {
                const int kglob = j0 + c;
                Ss[(i0 + r) * SS_LD + kglob] =
                    (kglob <= qglob) ? acc[r][c] * scale : -3.0e38f;
            }
        }
    }
    __syncthreads();

    // --- phase 2: softmax ---
    {
        const int row = tid >> 2;
        const int c   = tid & 3;
        float m = -3.4e38f;
        for (int j = c; j < kvlen; j += 4)
            m = fmaxf(m, Ss[row * SS_LD + j]);
        m = fmaxf(m, __shfl_xor_sync(0xffffffffu, m, 1));
        m = fmaxf(m, __shfl_xor_sync(0xffffffffu, m, 2));
        float s = 0.0f;
        for (int j = c; j < kvlen; j += 4) {
            const float e = __expf(Ss[row * SS_LD + j] - m);
            Ss[row * SS_LD + j] = e;
            s += e;
        }
        s += __shfl_xor_sync(0xffffffffu, s, 1);
        s += __shfl_xor_sync(0xffffffffu, s, 2);
        if (c == 0) rinv[row] = 1.0f / s;
    }
    __syncthreads();

    // --- phase 3: O = P V ---
    {
        const int d0 = tx * 4;
        float acc[4][4];
#pragma unroll
        for (int r = 0; r < 4; ++r)
#pragma unroll
            for (int c = 0; c < 4; ++c) acc[r][c] = 0.0f;

#pragma unroll 8
        for (int j = 0; j < kvlen; ++j) {
            const float4 bv = *(const float4*)(Vs + j * 64 + d0);
            const float bb[4] = {bv.x, bv.y, bv.z, bv.w};
            float a[4];
#pragma unroll
            for (int r = 0; r < 4; ++r) a[r] = Ss[(i0 + r) * SS_LD + j];
#pragma unroll
            for (int r = 0; r < 4; ++r)
#pragma unroll
                for (int c = 0; c < 4; ++c)
                    acc[r][c] = fmaf(a[r], bb[c], acc[r][c]);
        }

        float* Og = Out + ((size_t)b * SEQ + qt * 64) * HDIM;
#pragma unroll
        for (int r = 0; r < 4; ++r) {
            const float inv = rinv[i0 + r];
            float4 v;
            v.x = acc[r][0] * inv; v.y = acc[r][1] * inv;
            v.z = acc[r][2] * inv; v.w = acc[r][3] * inv;
            *(float4*)(Og + (size_t)(i0 + r) * HDIM + d0) = v;
        }
    }
}

// ---------------------------------------------------------------------------
extern "C" void kernel_launch(void* const* d_in, const int* in_sizes, int n_in,
                              void* d_out, int out_size)
{
    const float* X  = (const float*)d_in[0];   // [512,256,384]
    const float* Wk = (const float*)d_in[1];   // [384,64]
    const float* Wq = (const float*)d_in[2];   // [384,64]
    const float* Wv = (const float*)d_in[3];   // [384,64]
    float* Out = (float*)d_out;                // [512,256,64]

    (void)in_sizes; (void)n_in; (void)out_size;

    cudaFuncSetAttribute(proj_kernel,
                         cudaFuncAttributeMaxDynamicSharedMemorySize, PJ_SMEM_BYTES);
    cudaFuncSetAttribute(attn_kernel,
                         cudaFuncAttributeMaxDynamicSharedMemorySize, SM_BYTES);

    wconv_kernel<<<288, 256>>>(Wq, Wk, Wv);
    proj_kernel<<<NROWS / 128, 256, PJ_SMEM_BYTES>>>(X);

    dim3 grid(SEQ / 64, BATCH);
    attn_kernel<<<grid, 256, SM_BYTES>>>(Out);
}